// round 16
// baseline (speedup 1.0000x reference)
#include <cuda_runtime.h>
#include <cuda_fp16.h>
#include <cstdint>
#include <math.h>

#define M_DIM 16384
#define K_DIM 768
#define N_DIM 3072

// ---------------- scratch (no cudaMalloc allowed) ----------------
__device__ uint16_t g_A[M_DIM * K_DIM];    // fp16 bits, LN output
__device__ uint16_t g_B[N_DIM * K_DIM];    // fp16 bits, W transposed [N, K]

// ---------------- helpers ----------------
__device__ __forceinline__ uint32_t smem_u32(const void* p) {
    uint32_t a;
    asm("{ .reg .u64 t; cvta.to.shared.u64 t, %1; cvt.u32.u64 %0, t; }" : "=r"(a) : "l"(p));
    return a;
}
__device__ __forceinline__ uint32_t pack_h2(float lo, float hi) {
    uint32_t r;
    asm("cvt.rn.f16x2.f32 %0, %1, %2;" : "=r"(r) : "f"(hi), "f"(lo));
    return r;
}
__device__ __forceinline__ void cp_async16(uint32_t dst, const void* src) {
    asm volatile("cp.async.cg.shared.global [%0], [%1], 16;"
                 :: "r"(dst), "l"(__cvta_generic_to_global(src)) : "memory");
}
#define CP_COMMIT() asm volatile("cp.async.commit_group;" ::: "memory")
#define CP_WAIT(n)  asm volatile("cp.async.wait_group %0;" :: "n"(n) : "memory")

__device__ __forceinline__ void ldmatrix_x4(uint32_t* r, uint32_t addr) {
    asm volatile("ldmatrix.sync.aligned.m8n8.x4.shared.b16 {%0,%1,%2,%3}, [%4];"
                 : "=r"(r[0]), "=r"(r[1]), "=r"(r[2]), "=r"(r[3]) : "r"(addr));
}
__device__ __forceinline__ void mma_f16(float* d, const uint32_t* a,
                                        uint32_t b0, uint32_t b1) {
    asm volatile(
        "mma.sync.aligned.m16n8k16.row.col.f32.f16.f16.f32 "
        "{%0,%1,%2,%3}, {%4,%5,%6,%7}, {%8,%9}, {%0,%1,%2,%3};"
        : "+f"(d[0]), "+f"(d[1]), "+f"(d[2]), "+f"(d[3])
        : "r"(a[0]), "r"(a[1]), "r"(a[2]), "r"(a[3]), "r"(b0), "r"(b1));
}
__device__ __forceinline__ float gelu_exact(float h) {
    return 0.5f * h * (1.0f + erff(h * 0.70710678118654752f));
}

// ---------------------------------------------------------------------------
// Kernel 1: MERGED prep. Blocks [0, 4096): LayerNorm -> fp16 (4 rows each).
// Blocks [4096, 4384): transpose W [K,N] -> [N,K] fp16 (64K x 32N tile).
// Both paths' math is bit-identical to the R13 kernels.
// ---------------------------------------------------------------------------
#define LN_BLOCKS (M_DIM / 4)          // 4096
#define WT_BLOCKS ((N_DIM / 32) * (K_DIM / 64))   // 96 * 12 = 1152? no: 96*12
// N_DIM/32 = 96 tiles along N, K_DIM/64 = 12 tiles along K -> 1152? careful:
// original wt grid was (96, 12) = 1152 blocks of 256 thr. Use that.
#undef WT_BLOCKS
#define WT_BLOCKS ((N_DIM / 32) * (K_DIM / 64))   // 1152

__global__ __launch_bounds__(256) void prep_kernel(
    const float* __restrict__ x,
    const float* __restrict__ gamma,
    const float* __restrict__ beta,
    const float* __restrict__ W)
{
    const int tid = threadIdx.x;
    const int bid = blockIdx.x;

    if (bid < LN_BLOCKS) {
        // ---------------- LayerNorm path ----------------
        const int rloc = tid >> 6;
        const int t = tid & 63;
        const int row = bid * 4 + rloc;
        const float4* xr = (const float4*)(x + (size_t)row * K_DIM);

        float4 v[3];
        #pragma unroll
        for (int j = 0; j < 3; j++) v[j] = xr[t + 64 * j];

        float s = 0.0f, s2 = 0.0f;
        #pragma unroll
        for (int j = 0; j < 3; j++) {
            s  += v[j].x + v[j].y + v[j].z + v[j].w;
            s2 += v[j].x * v[j].x + v[j].y * v[j].y
                + v[j].z * v[j].z + v[j].w * v[j].w;
        }
        #pragma unroll
        for (int off = 16; off > 0; off >>= 1) {
            s  += __shfl_xor_sync(0xffffffffu, s,  off);
            s2 += __shfl_xor_sync(0xffffffffu, s2, off);
        }
        __shared__ float red[4][2][2];
        const int wir = (t >> 5);
        if ((t & 31) == 0) { red[rloc][wir][0] = s; red[rloc][wir][1] = s2; }
        __syncthreads();
        s  = red[rloc][0][0] + red[rloc][1][0];
        s2 = red[rloc][0][1] + red[rloc][1][1];

        const float inv_n = 1.0f / (float)K_DIM;
        const float mu  = s * inv_n;
        const float var = fmaxf(s2 * inv_n - mu * mu, 0.0f);
        const float rstd = rsqrtf(var + 1e-12f);

        uint2* outr = (uint2*)(g_A + (size_t)row * K_DIM);
        #pragma unroll
        for (int j = 0; j < 3; j++) {
            const float4 g = ((const float4*)gamma)[t + 64 * j];
            const float4 be = ((const float4*)beta)[t + 64 * j];
            uint2 o;
            o.x = pack_h2((v[j].x - mu) * rstd * g.x + be.x,
                          (v[j].y - mu) * rstd * g.y + be.y);
            o.y = pack_h2((v[j].z - mu) * rstd * g.z + be.z,
                          (v[j].w - mu) * rstd * g.w + be.w);
            outr[t + 64 * j] = o;
        }
    } else {
        // ---------------- W transpose path ----------------
        __shared__ float tile[64][33];
        const int b = bid - LN_BLOCKS;
        const int tx = tid & 31, ty = tid >> 5;    // (32, 8)
        const int n0 = (b % (N_DIM / 32)) * 32;
        const int k0 = (b / (N_DIM / 32)) * 64;

        #pragma unroll
        for (int j = 0; j < 8; j++)
            tile[ty + 8 * j][tx] = W[(size_t)(k0 + ty + 8 * j) * N_DIM + n0 + tx];
        __syncthreads();

        uint4 o;
        o.x = pack_h2(tile[ty * 8 + 0][tx], tile[ty * 8 + 1][tx]);
        o.y = pack_h2(tile[ty * 8 + 2][tx], tile[ty * 8 + 3][tx]);
        o.z = pack_h2(tile[ty * 8 + 4][tx], tile[ty * 8 + 5][tx]);
        o.w = pack_h2(tile[ty * 8 + 6][tx], tile[ty * 8 + 7][tx]);
        *(uint4*)&g_B[(size_t)(n0 + tx) * K_DIM + k0 + ty * 8] = o;
    }
}

// ---------------------------------------------------------------------------
// Kernel 2: fp16 GEMM (R13 structure: CTA 128x128, warp 32x64, BK=32,
// phase unroll with immediate offsets). Changed: 4 stages + CP_WAIT(2),
// dynamic smem 80KB (2 CTAs/SM preserved). Math identical to R13.
// ---------------------------------------------------------------------------
#define BM 128
#define BN 128
#define BK 32
#define ROWH 40
#define NSTEP 24
#define NSTAGE 4
#define STG_A (BM * ROWH * 2)     // 10240 B
#define STG_B (BN * ROWH * 2)     // 10240 B
#define CHUNK2 (64 * ROWH * 2)    // +64 rows = 5120 B
#define MT16 (16 * ROWH * 2)      // +16 rows = 1280 B
#define SMEM_BYTES (NSTAGE * (STG_A + STG_B))   // 81920 B

__global__ __launch_bounds__(256, 2) void gemm_f16_kernel(
    const float* __restrict__ bias, float* __restrict__ C)
{
    extern __shared__ uint16_t sdyn[];

    const int tid = threadIdx.x;
    const int wid = tid >> 5, lane = tid & 31;
    const int bn = blockIdx.x * BN;
    const int bm = blockIdx.y * BM;
    const int wm = (wid >> 1) * 32;   // 4 warps along M
    const int wn = (wid & 1) * 64;    // 2 warps along N

    float acc[2][8][4];
    #pragma unroll
    for (int mt = 0; mt < 2; mt++)
        #pragma unroll
        for (int nt = 0; nt < 8; nt++)
            #pragma unroll
            for (int q = 0; q < 4; q++) acc[mt][nt][q] = 0.0f;

    const uint32_t sA0 = smem_u32(sdyn);
    const uint32_t sB0 = sA0 + NSTAGE * STG_A;

    // ---- loop-invariant addresses ----
    const int r_ld = tid >> 2;             // 0..63
    const int c_ld = (tid & 3) * 8;

    uint32_t awA[NSTAGE], awB[NSTAGE];     // cp.async write bases (chunk 0)
    uint32_t raA[NSTAGE], raB[NSTAGE];     // ldmatrix read bases (mt=0, kk=0)
    #pragma unroll
    for (int s = 0; s < NSTAGE; s++) {
        awA[s] = sA0 + s * STG_A + (uint32_t)(r_ld * ROWH + c_ld) * 2;
        awB[s] = sB0 + s * STG_B + (uint32_t)(r_ld * ROWH + c_ld) * 2;
        raA[s] = sA0 + s * STG_A
               + (uint32_t)((wm + (lane & 15)) * ROWH) * 2 + (lane >> 4) * 16;
        raB[s] = sB0 + s * STG_B
               + (uint32_t)((wn + (lane & 15)) * ROWH) * 2 + (lane >> 4) * 16;
    }

    const uint16_t* pA = g_A + (size_t)(bm + r_ld) * K_DIM + c_ld;
    const uint16_t* pB = g_B + (size_t)(bn + r_ld) * K_DIM + c_ld;
    const size_t rowskip = (size_t)64 * K_DIM;

    // ---- prologue: steps 0,1,2 into stages 0,1,2 ----
    #pragma unroll
    for (int s = 0; s < 3; s++) {
        cp_async16(awA[s],          pA + s * BK);
        cp_async16(awA[s] + CHUNK2, pA + s * BK + rowskip);
        cp_async16(awB[s],          pB + s * BK);
        cp_async16(awB[s] + CHUNK2, pB + s * BK + rowskip);
        CP_COMMIT();
    }
    pA += 3 * BK;
    pB += 3 * BK;

    // ---- mainloop: 6 iterations x 4 compile-time phases ----
    for (int it = 0; it < NSTEP; it += 4) {
        #pragma unroll
        for (int ph = 0; ph < 4; ph++) {
            const int step = it + ph;          // stage == ph
            if (step < NSTEP - 2)      { CP_WAIT(2); }
            else if (step < NSTEP - 1) { CP_WAIT(1); }
            else                       { CP_WAIT(0); }
            __syncthreads();

            // prefetch step+3 into stage (ph+3)%4 (read last at step-1)
            if (step + 3 < NSTEP) {
                const int ps = (ph + 3) & 3;
                cp_async16(awA[ps],          pA);
                cp_async16(awA[ps] + CHUNK2, pA + rowskip);
                cp_async16(awB[ps],          pB);
                cp_async16(awB[ps] + CHUNK2, pB + rowskip);
                CP_COMMIT();
                pA += BK;
                pB += BK;
            }

            #pragma unroll
            for (int kk = 0; kk < 2; kk++) {
                uint32_t a[2][4];
                #pragma unroll
                for (int mt = 0; mt < 2; mt++)
                    ldmatrix_x4(a[mt], raA[ph] + mt * MT16 + kk * 32);
                uint32_t b[4][4];
                #pragma unroll
                for (int g = 0; g < 4; g++)
                    ldmatrix_x4(b[g], raB[ph] + g * MT16 + kk * 32);
                #pragma unroll
                for (int mt = 0; mt < 2; mt++)
                    #pragma unroll
                    for (int nt = 0; nt < 8; nt++)
                        mma_f16(acc[mt][nt], a[mt],
                                b[nt >> 1][nt & 1], b[nt >> 1][2 + (nt & 1)]);
            }
        }
    }

    // ---- epilogue: bias + exact erf GELU ----
    const int r0 = bm + wm + (lane >> 2);
    const int c0 = bn + wn + (lane & 3) * 2;
    #pragma unroll
    for (int mt = 0; mt < 2; mt++) {
        #pragma unroll
        for (int nt = 0; nt < 8; nt++) {
            const int col = c0 + nt * 8;
            const float b0 = __ldg(&bias[col]), b1 = __ldg(&bias[col + 1]);
            #pragma unroll
            for (int half = 0; half < 2; half++) {
                const int row = r0 + mt * 16 + half * 8;
                float2 o;
                o.x = gelu_exact(acc[mt][nt][half * 2 + 0] + b0);
                o.y = gelu_exact(acc[mt][nt][half * 2 + 1] + b1);
                *(float2*)&C[(size_t)row * N_DIM + col] = o;
            }
        }
    }
}

// ---------------------------------------------------------------------------
extern "C" void kernel_launch(void* const* d_in, const int* in_sizes, int n_in,
                              void* d_out, int out_size)
{
    const float* x     = (const float*)d_in[0];
    const float* gamma = (const float*)d_in[1];
    const float* beta  = (const float*)d_in[2];
    const float* W     = (const float*)d_in[3];
    const float* b     = (const float*)d_in[4];
    float* out = (float*)d_out;

    cudaFuncSetAttribute(gemm_f16_kernel,
                         cudaFuncAttributeMaxDynamicSharedMemorySize, SMEM_BYTES);

    prep_kernel<<<LN_BLOCKS + WT_BLOCKS, 256>>>(x, gamma, beta, W);
    gemm_f16_kernel<<<dim3(N_DIM / BN, M_DIM / BM), 256, SMEM_BYTES>>>(b, out);
}

// round 17
// speedup vs baseline: 1.0805x; 1.0805x over previous
#include <cuda_runtime.h>
#include <cuda_fp16.h>
#include <cstdint>
#include <math.h>

#define M_DIM 16384
#define K_DIM 768
#define N_DIM 3072

// ---------------- scratch (no cudaMalloc allowed) ----------------
__device__ uint16_t g_A[M_DIM * K_DIM];    // fp16 bits, LN output
__device__ uint16_t g_B[N_DIM * K_DIM];    // fp16 bits, W transposed [N, K]

// ---------------- helpers ----------------
__device__ __forceinline__ uint32_t smem_u32(const void* p) {
    uint32_t a;
    asm("{ .reg .u64 t; cvta.to.shared.u64 t, %1; cvt.u32.u64 %0, t; }" : "=r"(a) : "l"(p));
    return a;
}
__device__ __forceinline__ uint32_t pack_h2(float lo, float hi) {
    uint32_t r;
    asm("cvt.rn.f16x2.f32 %0, %1, %2;" : "=r"(r) : "f"(hi), "f"(lo));
    return r;
}
__device__ __forceinline__ void cp_async16(uint32_t dst, const void* src) {
    asm volatile("cp.async.cg.shared.global [%0], [%1], 16;"
                 :: "r"(dst), "l"(__cvta_generic_to_global(src)) : "memory");
}
#define CP_COMMIT() asm volatile("cp.async.commit_group;" ::: "memory")
#define CP_WAIT(n)  asm volatile("cp.async.wait_group %0;" :: "n"(n) : "memory")

__device__ __forceinline__ void ldmatrix_x4(uint32_t* r, uint32_t addr) {
    asm volatile("ldmatrix.sync.aligned.m8n8.x4.shared.b16 {%0,%1,%2,%3}, [%4];"
                 : "=r"(r[0]), "=r"(r[1]), "=r"(r[2]), "=r"(r[3]) : "r"(addr));
}
__device__ __forceinline__ void mma_f16(float* d, const uint32_t* a,
                                        uint32_t b0, uint32_t b1) {
    asm volatile(
        "mma.sync.aligned.m16n8k16.row.col.f32.f16.f16.f32 "
        "{%0,%1,%2,%3}, {%4,%5,%6,%7}, {%8,%9}, {%0,%1,%2,%3};"
        : "+f"(d[0]), "+f"(d[1]), "+f"(d[2]), "+f"(d[3])
        : "r"(a[0]), "r"(a[1]), "r"(a[2]), "r"(a[3]), "r"(b0), "r"(b1));
}
__device__ __forceinline__ float gelu_exact(float h) {
    return 0.5f * h * (1.0f + erff(h * 0.70710678118654752f));
}

// ---------------------------------------------------------------------------
// Kernel 1: MERGED prep (R16 version — measured win).
// Blocks [0, 4096): LayerNorm -> fp16 (4 rows each).
// Blocks [4096, 4096+1152): transpose W [K,N] -> [N,K] fp16 (64K x 32N tile).
// ---------------------------------------------------------------------------
#define LN_BLOCKS (M_DIM / 4)                      // 4096
#define WT_BLOCKS ((N_DIM / 32) * (K_DIM / 64))    // 1152

__global__ __launch_bounds__(256) void prep_kernel(
    const float* __restrict__ x,
    const float* __restrict__ gamma,
    const float* __restrict__ beta,
    const float* __restrict__ W)
{
    const int tid = threadIdx.x;
    const int bid = blockIdx.x;

    if (bid < LN_BLOCKS) {
        // ---------------- LayerNorm path ----------------
        const int rloc = tid >> 6;
        const int t = tid & 63;
        const int row = bid * 4 + rloc;
        const float4* xr = (const float4*)(x + (size_t)row * K_DIM);

        float4 v[3];
        #pragma unroll
        for (int j = 0; j < 3; j++) v[j] = xr[t + 64 * j];

        float s = 0.0f, s2 = 0.0f;
        #pragma unroll
        for (int j = 0; j < 3; j++) {
            s  += v[j].x + v[j].y + v[j].z + v[j].w;
            s2 += v[j].x * v[j].x + v[j].y * v[j].y
                + v[j].z * v[j].z + v[j].w * v[j].w;
        }
        #pragma unroll
        for (int off = 16; off > 0; off >>= 1) {
            s  += __shfl_xor_sync(0xffffffffu, s,  off);
            s2 += __shfl_xor_sync(0xffffffffu, s2, off);
        }
        __shared__ float red[4][2][2];
        const int wir = (t >> 5);
        if ((t & 31) == 0) { red[rloc][wir][0] = s; red[rloc][wir][1] = s2; }
        __syncthreads();
        s  = red[rloc][0][0] + red[rloc][1][0];
        s2 = red[rloc][0][1] + red[rloc][1][1];

        const float inv_n = 1.0f / (float)K_DIM;
        const float mu  = s * inv_n;
        const float var = fmaxf(s2 * inv_n - mu * mu, 0.0f);
        const float rstd = rsqrtf(var + 1e-12f);

        uint2* outr = (uint2*)(g_A + (size_t)row * K_DIM);
        #pragma unroll
        for (int j = 0; j < 3; j++) {
            const float4 g = ((const float4*)gamma)[t + 64 * j];
            const float4 be = ((const float4*)beta)[t + 64 * j];
            uint2 o;
            o.x = pack_h2((v[j].x - mu) * rstd * g.x + be.x,
                          (v[j].y - mu) * rstd * g.y + be.y);
            o.y = pack_h2((v[j].z - mu) * rstd * g.z + be.z,
                          (v[j].w - mu) * rstd * g.w + be.w);
            outr[t + 64 * j] = o;
        }
    } else {
        // ---------------- W transpose path ----------------
        __shared__ float tile[64][33];
        const int b = bid - LN_BLOCKS;
        const int tx = tid & 31, ty = tid >> 5;    // (32, 8)
        const int n0 = (b % (N_DIM / 32)) * 32;
        const int k0 = (b / (N_DIM / 32)) * 64;

        #pragma unroll
        for (int j = 0; j < 8; j++)
            tile[ty + 8 * j][tx] = W[(size_t)(k0 + ty + 8 * j) * N_DIM + n0 + tx];
        __syncthreads();

        uint4 o;
        o.x = pack_h2(tile[ty * 8 + 0][tx], tile[ty * 8 + 1][tx]);
        o.y = pack_h2(tile[ty * 8 + 2][tx], tile[ty * 8 + 3][tx]);
        o.z = pack_h2(tile[ty * 8 + 4][tx], tile[ty * 8 + 5][tx]);
        o.w = pack_h2(tile[ty * 8 + 6][tx], tile[ty * 8 + 7][tx]);
        *(uint4*)&g_B[(size_t)(n0 + tx) * K_DIM + k0 + ty * 8] = o;
    }
}

// ---------------------------------------------------------------------------
// Kernel 2: fp16 GEMM — exact R13 version (measured best: ~277us).
// CTA 128x128, warp 32x64, BK=32, 3-stage STATIC smem, CP_WAIT(1),
// phase-of-3 unroll (all smem offsets immediates).
// ---------------------------------------------------------------------------
#define BM 128
#define BN 128
#define BK 32
#define ROWH 40
#define NSTEP 24
#define NSTAGE 3
#define STG_A (BM * ROWH * 2)     // 10240 B
#define STG_B (BN * ROWH * 2)     // 10240 B
#define CHUNK2 (64 * ROWH * 2)    // +64 rows = 5120 B

__global__ __launch_bounds__(256, 2) void gemm_f16_kernel(
    const float* __restrict__ bias, float* __restrict__ C)
{
    __shared__ uint16_t As[NSTAGE][BM * ROWH];
    __shared__ uint16_t Bs[NSTAGE][BN * ROWH];

    const int tid = threadIdx.x;
    const int wid = tid >> 5, lane = tid & 31;
    const int bn = blockIdx.x * BN;
    const int bm = blockIdx.y * BM;
    const int wm = (wid >> 1) * 32;   // 4 warps along M
    const int wn = (wid & 1) * 64;    // 2 warps along N

    float acc[2][8][4];
    #pragma unroll
    for (int mt = 0; mt < 2; mt++)
        #pragma unroll
        for (int nt = 0; nt < 8; nt++)
            #pragma unroll
            for (int q = 0; q < 4; q++) acc[mt][nt][q] = 0.0f;

    const uint32_t sA0 = smem_u32(&As[0][0]);
    const uint32_t sB0 = smem_u32(&Bs[0][0]);

    // ---- loop-invariant addresses ----
    const int r_ld = tid >> 2;             // 0..63
    const int c_ld = (tid & 3) * 8;

    uint32_t awA[NSTAGE], awB[NSTAGE];     // cp.async write bases (chunk 0)
    uint32_t raA[NSTAGE], raB[NSTAGE];     // ldmatrix read bases (mt=0, kk=0)
    #pragma unroll
    for (int s = 0; s < NSTAGE; s++) {
        awA[s] = sA0 + s * STG_A + (uint32_t)(r_ld * ROWH + c_ld) * 2;
        awB[s] = sB0 + s * STG_B + (uint32_t)(r_ld * ROWH + c_ld) * 2;
        raA[s] = sA0 + s * STG_A
               + (uint32_t)((wm + (lane & 15)) * ROWH) * 2 + (lane >> 4) * 16;
        raB[s] = sB0 + s * STG_B
               + (uint32_t)((wn + (lane & 15)) * ROWH) * 2 + (lane >> 4) * 16;
    }

    const uint16_t* pA = g_A + (size_t)(bm + r_ld) * K_DIM + c_ld;
    const uint16_t* pB = g_B + (size_t)(bn + r_ld) * K_DIM + c_ld;
    const size_t rowskip = (size_t)64 * K_DIM;

    // ---- prologue: steps 0,1 into stages 0,1 ----
    #pragma unroll
    for (int s = 0; s < 2; s++) {
        cp_async16(awA[s],          pA + s * BK);
        cp_async16(awA[s] + CHUNK2, pA + s * BK + rowskip);
        cp_async16(awB[s],          pB + s * BK);
        cp_async16(awB[s] + CHUNK2, pB + s * BK + rowskip);
        CP_COMMIT();
    }
    pA += 2 * BK;
    pB += 2 * BK;

    // ---- mainloop: 8 iterations x 3 compile-time phases ----
    for (int it = 0; it < NSTEP; it += 3) {
        #pragma unroll
        for (int ph = 0; ph < 3; ph++) {
            const int step = it + ph;          // stage == ph
            if (step < NSTEP - 1) { CP_WAIT(1); } else { CP_WAIT(0); }
            __syncthreads();

            // prefetch step+2 into stage (ph+2)%3 (read last at step-1)
            if (step + 2 < NSTEP) {
                const int ps = (ph + 2) % 3;
                cp_async16(awA[ps],          pA);
                cp_async16(awA[ps] + CHUNK2, pA + rowskip);
                cp_async16(awB[ps],          pB);
                cp_async16(awB[ps] + CHUNK2, pB + rowskip);
                CP_COMMIT();
                pA += BK;
                pB += BK;
            }

            #pragma unroll
            for (int kk = 0; kk < 2; kk++) {
                uint32_t a[2][4];
                #pragma unroll
                for (int mt = 0; mt < 2; mt++)
                    ldmatrix_x4(a[mt], raA[ph] + mt * (16 * ROWH * 2) + kk * 32);
                uint32_t b[4][4];
                #pragma unroll
                for (int g = 0; g < 4; g++)
                    ldmatrix_x4(b[g], raB[ph] + g * (16 * ROWH * 2) + kk * 32);
                #pragma unroll
                for (int mt = 0; mt < 2; mt++)
                    #pragma unroll
                    for (int nt = 0; nt < 8; nt++)
                        mma_f16(acc[mt][nt], a[mt],
                                b[nt >> 1][nt & 1], b[nt >> 1][2 + (nt & 1)]);
            }
        }
    }

    // ---- epilogue: bias + exact erf GELU ----
    const int r0 = bm + wm + (lane >> 2);
    const int c0 = bn + wn + (lane & 3) * 2;
    #pragma unroll
    for (int mt = 0; mt < 2; mt++) {
        #pragma unroll
        for (int nt = 0; nt < 8; nt++) {
            const int col = c0 + nt * 8;
            const float b0 = __ldg(&bias[col]), b1 = __ldg(&bias[col + 1]);
            #pragma unroll
            for (int half = 0; half < 2; half++) {
                const int row = r0 + mt * 16 + half * 8;
                float2 o;
                o.x = gelu_exact(acc[mt][nt][half * 2 + 0] + b0);
                o.y = gelu_exact(acc[mt][nt][half * 2 + 1] + b1);
                *(float2*)&C[(size_t)row * N_DIM + col] = o;
            }
        }
    }
}

// ---------------------------------------------------------------------------
extern "C" void kernel_launch(void* const* d_in, const int* in_sizes, int n_in,
                              void* d_out, int out_size)
{
    const float* x     = (const float*)d_in[0];
    const float* gamma = (const float*)d_in[1];
    const float* beta  = (const float*)d_in[2];
    const float* W     = (const float*)d_in[3];
    const float* b     = (const float*)d_in[4];
    float* out = (float*)d_out;

    prep_kernel<<<LN_BLOCKS + WT_BLOCKS, 256>>>(x, gamma, beta, W);
    gemm_f16_kernel<<<dim3(N_DIM / BN, M_DIM / BM), 256>>>(b, out);
}